// round 2
// baseline (speedup 1.0000x reference)
#include <cuda_runtime.h>
#include <cuda_bf16.h>
#include <math.h>

#define SEQ   2048
#define NH    16
#define NKV   2
#define HD    128
#define QSZ   (NH * HD)            // 2048
#define KVSZ  (NKV * HD)           // 256
#define QKVN  (QSZ + 2 * KVSZ)     // 2560
#define HID   2048
#define GROUPS (NH / NKV)          // 8

// ---------------- scratch (device globals; no allocs allowed) ----------------
__device__ float g_qkv[SEQ * QKVN];        // raw qkv projection
__device__ float g_q[NH * SEQ * HD];       // rope'd + scaled q, head-major
__device__ float g_k[NKV * SEQ * HD];      // rope'd k, head-major
__device__ float g_v[NKV * SEQ * HD];      // v, head-major
__device__ float g_attn[SEQ * QSZ];        // attention output [s][h*HD+d]
__device__ int   g_pos[SEQ];
__device__ int   g_segstart[SEQ];
__device__ float g_invf[HD / 2];

// ---------------- prep: decode positions (int32/int64), seg scan ----------------
__global__ void prep_kernel(const int* __restrict__ words) {
    __shared__ int chunk_last[256];
    int tid = threadIdx.x;
    // int64 arange -> words[1] (high word of element 0) == 0 ; int32 arange -> words[1] == 1
    int is64 = (words[1] == 0) ? 1 : 0;

    if (tid < HD / 2) {
        g_invf[tid] = (float)(1.0 / pow(1.0e6, (double)(2 * tid) / (double)HD));
    }

    int base = tid * 8;
    int local_pos[8];
    int run = -1;
    #pragma unroll
    for (int e = 0; e < 8; e++) {
        int i = base + e;
        int p = is64 ? words[2 * i] : words[i];
        if (p < 0) p = 0;
        local_pos[e] = p;
        g_pos[i] = p;
        if (p == 0) run = i;
    }
    chunk_last[tid] = run;
    __syncthreads();
    if (tid == 0) {
        int m = -1;
        for (int t = 0; t < 256; t++) {
            int c = chunk_last[t];
            chunk_last[t] = m;          // exclusive running max
            m = max(m, c);
        }
    }
    __syncthreads();
    int m = chunk_last[tid];
    #pragma unroll
    for (int e = 0; e < 8; e++) {
        int i = base + e;
        if (local_pos[e] == 0) m = i;
        g_segstart[i] = max(m, 0);
    }
}

// ---------------- SGEMM: C[M,N] = A[M,K] @ B[K,N] (+bias), 128x128x8, 8x8 micro ----------------
__global__ __launch_bounds__(256) void sgemm_bias(
    const float* __restrict__ A, const float* __restrict__ B,
    const float* __restrict__ bias, float* __restrict__ C,
    int M, int N, int K)
{
    __shared__ float As[8][128];
    __shared__ float Bs[8][128];
    int tid = threadIdx.x;
    int bx = blockIdx.x, by = blockIdx.y;
    int tx = tid & 15, ty = tid >> 4;

    int arow = tid >> 1;
    int acol = (tid & 1) * 4;
    int brow = tid >> 5;
    int bcol = (tid & 31) * 4;

    const float* Aptr = A + (size_t)(by * 128 + arow) * K + acol;
    const float* Bptr = B + (size_t)brow * N + bx * 128 + bcol;

    float acc[8][8];
    #pragma unroll
    for (int i = 0; i < 8; i++)
        #pragma unroll
        for (int j = 0; j < 8; j++) acc[i][j] = 0.f;

    for (int k0 = 0; k0 < K; k0 += 8) {
        float4 a = *(const float4*)(Aptr + k0);
        As[acol + 0][arow] = a.x;
        As[acol + 1][arow] = a.y;
        As[acol + 2][arow] = a.z;
        As[acol + 3][arow] = a.w;
        float4 b = *(const float4*)(Bptr + (size_t)k0 * N);
        *(float4*)&Bs[brow][bcol] = b;
        __syncthreads();
        #pragma unroll
        for (int kk = 0; kk < 8; kk++) {
            float ar[8], br[8];
            float4 a0 = *(float4*)&As[kk][ty * 8];
            float4 a1 = *(float4*)&As[kk][ty * 8 + 4];
            float4 b0 = *(float4*)&Bs[kk][tx * 8];
            float4 b1 = *(float4*)&Bs[kk][tx * 8 + 4];
            ar[0]=a0.x; ar[1]=a0.y; ar[2]=a0.z; ar[3]=a0.w;
            ar[4]=a1.x; ar[5]=a1.y; ar[6]=a1.z; ar[7]=a1.w;
            br[0]=b0.x; br[1]=b0.y; br[2]=b0.z; br[3]=b0.w;
            br[4]=b1.x; br[5]=b1.y; br[6]=b1.z; br[7]=b1.w;
            #pragma unroll
            for (int i = 0; i < 8; i++)
                #pragma unroll
                for (int j = 0; j < 8; j++)
                    acc[i][j] = fmaf(ar[i], br[j], acc[i][j]);
        }
        __syncthreads();
    }

    float bv[8];
    if (bias) {
        float4 q0 = *(const float4*)(bias + bx * 128 + tx * 8);
        float4 q1 = *(const float4*)(bias + bx * 128 + tx * 8 + 4);
        bv[0]=q0.x; bv[1]=q0.y; bv[2]=q0.z; bv[3]=q0.w;
        bv[4]=q1.x; bv[5]=q1.y; bv[6]=q1.z; bv[7]=q1.w;
    } else {
        #pragma unroll
        for (int j = 0; j < 8; j++) bv[j] = 0.f;
    }

    #pragma unroll
    for (int i = 0; i < 8; i++) {
        int row = by * 128 + ty * 8 + i;
        float* Crow = C + (size_t)row * N + bx * 128 + tx * 8;
        float4 r0, r1;
        r0.x = acc[i][0] + bv[0]; r0.y = acc[i][1] + bv[1];
        r0.z = acc[i][2] + bv[2]; r0.w = acc[i][3] + bv[3];
        r1.x = acc[i][4] + bv[4]; r1.y = acc[i][5] + bv[5];
        r1.z = acc[i][6] + bv[6]; r1.w = acc[i][7] + bv[7];
        *(float4*)(Crow)     = r0;
        *(float4*)(Crow + 4) = r1;
    }
}

// ---------------- RoPE + split into head-major q/k/v ----------------
__global__ void rope_split_kernel() {
    const int NQ = SEQ * NH * (HD / 2);          // q pairs
    const int NK = SEQ * NKV * (HD / 2);         // k pairs
    const int NV = SEQ * NKV * (HD / 4);         // v float4s
    int idx = blockIdx.x * blockDim.x + threadIdx.x;
    if (idx < NQ) {
        int s   = idx / (NH * (HD / 2));
        int rem = idx % (NH * (HD / 2));
        int h = rem >> 6, j = rem & 63;
        float invf = g_invf[j];
        float freq = (float)g_pos[s] * invf;
        float sn, cs;
        sincosf(freq, &sn, &cs);
        const float* row = g_qkv + (size_t)s * QKVN + h * HD + 2 * j;
        float x1 = row[0], x2 = row[1];
        const float qscale = 0.08838834764831845f;   // 1/sqrt(128)
        float* dst = g_q + ((size_t)h * SEQ + s) * HD + 2 * j;
        dst[0] = (x1 * cs - x2 * sn) * qscale;
        dst[1] = (x1 * sn + x2 * cs) * qscale;
        return;
    }
    idx -= NQ;
    if (idx < NK) {
        int s   = idx / (NKV * (HD / 2));
        int rem = idx % (NKV * (HD / 2));
        int h = rem >> 6, j = rem & 63;
        float invf = g_invf[j];
        float freq = (float)g_pos[s] * invf;
        float sn, cs;
        sincosf(freq, &sn, &cs);
        const float* row = g_qkv + (size_t)s * QKVN + QSZ + h * HD + 2 * j;
        float x1 = row[0], x2 = row[1];
        float* dst = g_k + ((size_t)h * SEQ + s) * HD + 2 * j;
        dst[0] = x1 * cs - x2 * sn;
        dst[1] = x1 * sn + x2 * cs;
        return;
    }
    idx -= NK;
    if (idx < NV) {
        int s = idx / (KVSZ / 4);
        int w = idx % (KVSZ / 4);
        int h = w >> 5;
        int d = (w * 4) & (HD - 1);
        float4 v = *(const float4*)(g_qkv + (size_t)s * QKVN + QSZ + KVSZ + w * 4);
        *(float4*)(g_v + ((size_t)h * SEQ + s) * HD + d) = v;
    }
}

// ---------------- flash attention: 64q x 64k tiles, online softmax ----------------
#define QT 64
#define KT 64
#define QPAD 132   // 128 + 4 keeps float4 alignment, dodges bank conflicts
#define SPAD 65

__global__ __launch_bounds__(256) void flash_attn_kernel() {
    extern __shared__ float sm[];
    float* Qs   = sm;                       // [64][132]
    float* Ks   = Qs + 64 * QPAD;           // [64][132]
    float* Vs   = Ks + 64 * QPAD;           // [64][128]
    float* Ss   = Vs + 64 * HD;             // [64][65] scores -> probs
    float* mbuf = Ss + 64 * SPAD;           // [64]
    float* lbuf = mbuf + 64;                // [64]
    float* abuf = lbuf + 64;                // [64]
    float* red  = abuf + 64;                // [64][4]
    __shared__ int s_ktmin;

    int tid = threadIdx.x;
    int tx = tid & 15, ty = tid >> 4;
    int qt = blockIdx.x;
    int h  = blockIdx.y;
    int kvh = h / GROUPS;
    int q0 = qt * QT;

    const float* qg = g_q + ((size_t)h * SEQ + q0) * HD;
    for (int it = tid; it < QT * HD; it += 256) {
        int r = it >> 7, c = it & 127;
        Qs[r * QPAD + c] = qg[it];
    }
    if (tid < QT) { mbuf[tid] = -1e30f; lbuf[tid] = 0.f; }
    if (tid == 0) {
        int mn = 0x7fffffff;
        for (int r = 0; r < QT; r++) mn = min(mn, g_segstart[q0 + r]);
        s_ktmin = mn >> 6;
    }
    float acc[4][8];
    #pragma unroll
    for (int i = 0; i < 4; i++)
        #pragma unroll
        for (int j = 0; j < 8; j++) acc[i][j] = 0.f;
    __syncthreads();

    int r0 = ty * 4;
    int c0 = tx * 4;

    for (int kt = s_ktmin; kt <= qt; kt++) {
        const float* kg = g_k + ((size_t)kvh * SEQ + kt * KT) * HD;
        const float* vg = g_v + ((size_t)kvh * SEQ + kt * KT) * HD;
        for (int it = tid; it < KT * HD; it += 256) {
            int r = it >> 7, c = it & 127;
            Ks[r * QPAD + c] = kg[it];
            Vs[r * HD + c]   = vg[it];
        }
        __syncthreads();

        // S = Q K^T (4x4 micro, float4 over k-dim)
        float sa[4][4];
        #pragma unroll
        for (int i = 0; i < 4; i++)
            #pragma unroll
            for (int j = 0; j < 4; j++) sa[i][j] = 0.f;
        #pragma unroll 2
        for (int kk = 0; kk < HD; kk += 4) {
            float4 a[4], b[4];
            #pragma unroll
            for (int i = 0; i < 4; i++) a[i] = *(float4*)&Qs[(r0 + i) * QPAD + kk];
            #pragma unroll
            for (int j = 0; j < 4; j++) b[j] = *(float4*)&Ks[(c0 + j) * QPAD + kk];
            #pragma unroll
            for (int i = 0; i < 4; i++)
                #pragma unroll
                for (int j = 0; j < 4; j++) {
                    sa[i][j] = fmaf(a[i].x, b[j].x, sa[i][j]);
                    sa[i][j] = fmaf(a[i].y, b[j].y, sa[i][j]);
                    sa[i][j] = fmaf(a[i].z, b[j].z, sa[i][j]);
                    sa[i][j] = fmaf(a[i].w, b[j].w, sa[i][j]);
                }
        }
        #pragma unroll
        for (int i = 0; i < 4; i++)
            #pragma unroll
            for (int j = 0; j < 4; j++)
                Ss[(r0 + i) * SPAD + c0 + j] = sa[i][j];
        __syncthreads();

        // partial row max (4 threads per row, 16 cols each)
        {
            int r = tid >> 2, qd = tid & 3;
            int sg = q0 + r;
            int tstart = g_segstart[sg];
            float mx = -1e30f;
            int cb = qd * 16;
            #pragma unroll
            for (int c = 0; c < 16; c++) {
                int t = kt * KT + cb + c;
                if (t <= sg && t >= tstart) mx = fmaxf(mx, Ss[r * SPAD + cb + c]);
            }
            red[r * 4 + qd] = mx;
        }
        __syncthreads();
        if (tid < QT) {
            int r = tid;
            float mx = fmaxf(fmaxf(red[r*4], red[r*4+1]), fmaxf(red[r*4+2], red[r*4+3]));
            float mold = mbuf[r];
            float mnew = fmaxf(mold, mx);
            abuf[r] = __expf(mold - mnew);   // mold==mnew==-1e30 -> exp(0)=1, l stays 0
            mbuf[r] = mnew;
        }
        __syncthreads();
        // exponentiate into probs
        {
            int r = tid >> 2, qd = tid & 3;
            int sg = q0 + r;
            int tstart = g_segstart[sg];
            float mnew = mbuf[r];
            float sum = 0.f;
            int cb = qd * 16;
            #pragma unroll
            for (int c = 0; c < 16; c++) {
                int t = kt * KT + cb + c;
                float p = 0.f;
                if (t <= sg && t >= tstart) p = __expf(Ss[r * SPAD + cb + c] - mnew);
                Ss[r * SPAD + cb + c] = p;
                sum += p;
            }
            red[r * 4 + qd] = sum;
        }
        __syncthreads();
        if (tid < QT) {
            int r = tid;
            lbuf[r] = lbuf[r] * abuf[r] + red[r*4] + red[r*4+1] + red[r*4+2] + red[r*4+3];
        }
        __syncthreads();

        // O = O*alpha + P V  (4 rows x 8 cols per thread)
        float al[4];
        #pragma unroll
        for (int i = 0; i < 4; i++) al[i] = abuf[r0 + i];
        #pragma unroll
        for (int i = 0; i < 4; i++)
            #pragma unroll
            for (int j = 0; j < 8; j++) acc[i][j] *= al[i];
        int oc = tx * 8;
        for (int kk = 0; kk < KT; kk++) {
            float p[4];
            #pragma unroll
            for (int i = 0; i < 4; i++) p[i] = Ss[(r0 + i) * SPAD + kk];
            float4 v0 = *(float4*)&Vs[kk * HD + oc];
            float4 v1 = *(float4*)&Vs[kk * HD + oc + 4];
            #pragma unroll
            for (int i = 0; i < 4; i++) {
                acc[i][0] = fmaf(p[i], v0.x, acc[i][0]);
                acc[i][1] = fmaf(p[i], v0.y, acc[i][1]);
                acc[i][2] = fmaf(p[i], v0.z, acc[i][2]);
                acc[i][3] = fmaf(p[i], v0.w, acc[i][3]);
                acc[i][4] = fmaf(p[i], v1.x, acc[i][4]);
                acc[i][5] = fmaf(p[i], v1.y, acc[i][5]);
                acc[i][6] = fmaf(p[i], v1.z, acc[i][6]);
                acc[i][7] = fmaf(p[i], v1.w, acc[i][7]);
            }
        }
        __syncthreads();   // protect Ks/Vs/Ss before next iteration's loads
    }

    // normalize + write [s][h*HD + d]
    #pragma unroll
    for (int i = 0; i < 4; i++) {
        float l = lbuf[r0 + i];
        float rn = (l > 0.f) ? 1.f / l : 0.f;
        int row = q0 + r0 + i;
        float* dst = g_attn + (size_t)row * QSZ + h * HD + tx * 8;
        float4 o0, o1;
        o0.x = acc[i][0]*rn; o0.y = acc[i][1]*rn; o0.z = acc[i][2]*rn; o0.w = acc[i][3]*rn;
        o1.x = acc[i][4]*rn; o1.y = acc[i][5]*rn; o1.z = acc[i][6]*rn; o1.w = acc[i][7]*rn;
        *(float4*)(dst)     = o0;
        *(float4*)(dst + 4) = o1;
    }
}

// ---------------- launch ----------------
extern "C" void kernel_launch(void* const* d_in, const int* in_sizes, int n_in,
                              void* d_out, int out_size) {
    const float* hidden = (const float*)d_in[0];
    const int*   posw   = (const int*)d_in[1];
    const float* w_qkv  = (const float*)d_in[2];
    const float* b_qkv  = (const float*)d_in[3];
    const float* w_o    = (const float*)d_in[4];
    float* out = (float*)d_out;

    void *p_qkv = nullptr, *p_attn = nullptr;
    cudaGetSymbolAddress(&p_qkv, g_qkv);
    cudaGetSymbolAddress(&p_attn, g_attn);

    prep_kernel<<<1, 256>>>(posw);

    sgemm_bias<<<dim3(QKVN / 128, SEQ / 128), 256>>>(
        hidden, w_qkv, b_qkv, (float*)p_qkv, SEQ, QKVN, HID);

    int total = SEQ * NH * (HD / 2) + SEQ * NKV * (HD / 2) + SEQ * NKV * (HD / 4);
    rope_split_kernel<<<(total + 255) / 256, 256>>>();

    size_t fa_smem = (size_t)(64 * QPAD * 2 + 64 * HD + 64 * SPAD + 64 * 3 + 256) * sizeof(float);
    cudaFuncSetAttribute(flash_attn_kernel,
                         cudaFuncAttributeMaxDynamicSharedMemorySize, (int)fa_smem);
    flash_attn_kernel<<<dim3(SEQ / QT, NH), 256, fa_smem>>>();

    sgemm_bias<<<dim3(HID / 128, SEQ / 128), 256>>>(
        (const float*)p_attn, w_o, nullptr, out, SEQ, HID, QSZ);
}